// round 7
// baseline (speedup 1.0000x reference)
#include <cuda_runtime.h>
#include <cuda_bf16.h>
#include <math.h>

// ---------------- problem dims ----------------
#define B_   64
#define S_   512
#define DIN  784
#define DEMB 600
#define DQK  64
#define DH2  200
#define DOUT 10
#define MROWS (B_*S_)   // 32768

// Eigen MT gebp K-panel size (confirmed bit-exact in R5): kc = 320
#define KC_MAIN 320

// ---------------- scratch (device globals: no allocation allowed) ----------------
__device__ unsigned int g_max_u;
static __device__ float d_spk1   [(size_t)MROWS*DEMB];
static __device__ float d_Q      [(size_t)MROWS*DQK];
static __device__ float d_K      [(size_t)MROWS*DQK];
static __device__ float d_V      [(size_t)MROWS*DEMB];
static __device__ float d_attn   [(size_t)B_*S_*S_];
static __device__ float d_attnout[(size_t)MROWS*DEMB];
static __device__ float d_spk2   [(size_t)MROWS*DH2];

// ---------------- packed fp32x2 helpers (lane-wise IEEE RN: bit-exact) ----------------
typedef unsigned long long ull;
__device__ __forceinline__ ull pack2(float lo, float hi) {
    ull r; asm("mov.b64 %0, {%1, %2};" : "=l"(r) : "f"(lo), "f"(hi)); return r;
}
__device__ __forceinline__ void unpack2(ull v, float& lo, float& hi) {
    asm("mov.b64 {%0, %1}, %2;" : "=f"(lo), "=f"(hi) : "l"(v));
}
__device__ __forceinline__ ull ffma2(ull a, ull b, ull c) {
    ull d; asm("fma.rn.f32x2 %0, %1, %2, %3;" : "=l"(d) : "l"(a), "l"(b), "l"(c)); return d;
}
__device__ __forceinline__ ull fadd2(ull a, ull b) {
    ull d; asm("add.rn.f32x2 %0, %1, %2;" : "=l"(d) : "l"(a), "l"(b)); return d;
}

// ---------------- kernels ----------------
__global__ void reset_kernel() { g_max_u = 0u; }

__global__ void reduce_max_kernel(const float* __restrict__ x, int n) {
    float m = 0.f;
    for (int i = blockIdx.x * blockDim.x + threadIdx.x; i < n; i += gridDim.x * blockDim.x)
        m = fmaxf(m, x[i]);
    #pragma unroll
    for (int o = 16; o; o >>= 1) m = fmaxf(m, __shfl_xor_sync(0xffffffffu, m, o));
    if ((threadIdx.x & 31) == 0) atomicMax(&g_max_u, __float_as_uint(m)); // x >= 0
}

// Tiled fp32 GEMM emulating Eigen gebp accumulation order (BIT-EXACT vs R5/R6):
//   per output: ascending-k fmaf chain, folded into a running total at kc
//   panel boundaries (last panel = remainder). FFMA2 pairs adjacent-ROW chains
//   into one instruction; each scalar slot's chain is unchanged.
//   A: [M,K] row-major; B: b_kn==0 -> [N,K], b_kn==1 -> [K,N]
//   batched via blockIdx.z with strides sA,sB,sC (res uses sC).
// Tiling: BM=128, BN=64, BK=8, 256 threads, 8x4 per-thread tile.
// Requires: M % 128 == 0, K % 8 == 0 (true for every call site).
#define BM 128
#define BN 64
#define BK 8
__global__ __launch_bounds__(256, 2)
void gemm_kernel(const float* __restrict__ A,
                 const float* __restrict__ Bm,
                 const float* __restrict__ bias,
                 const float* __restrict__ res,
                 float* __restrict__ C,
                 int M, int N, int K, int kc,
                 long long sA, long long sB, long long sC,
                 float alpha, int b_kn, int spike, float thr, int scaleA)
{
    __shared__ float As[2][BK][BM];
    __shared__ float Bs[2][BK][BN];

    long long bz = blockIdx.z;
    A  += bz * sA;
    Bm += bz * sB;
    C  += bz * sC;
    if (res) res += bz * sC;

    const int rowBase = blockIdx.y * BM;
    const int colBase = blockIdx.x * BN;
    const int t  = threadIdx.x;            // 256 threads
    const int tx = t & 15;                 // 16 cols of 4
    const int ty = t >> 4;                 // 16 rows of 8

    float sc = 1.0f;
    if (scaleA) sc = (__uint_as_float(g_max_u) > 1.0f) ? (1.0f / 255.0f) : 1.0f;

    // ---- staging register indices ----
    const int am = t >> 1;                 // A: float4 at (m=t>>1, k=(t&1)*4)
    const int ak = (t & 1) * 4;
    const int bn0 = t >> 2;                // B [N,K]: float2 at (n=t>>2, k=(t&3)*2)
    const int bk0 = (t & 3) * 2;
    const int bk1 = t >> 5;                // B [K,N]: 2 scalars at (k=t>>5, n=(t&31)*2)
    const int bn1 = (t & 31) * 2;

    float4 aReg;
    float  bReg0, bReg1;

    auto loadA = [&](int k0) {
        aReg = *reinterpret_cast<const float4*>(A + (long long)(rowBase + am) * K + (k0 + ak));
        aReg.x *= sc; aReg.y *= sc; aReg.z *= sc; aReg.w *= sc;
    };
    auto loadB = [&](int k0) {
        if (b_kn == 0) {
            int gn = colBase + bn0;
            if (gn < N) {
                float2 v = *reinterpret_cast<const float2*>(Bm + (long long)gn * K + (k0 + bk0));
                bReg0 = v.x; bReg1 = v.y;
            } else { bReg0 = 0.f; bReg1 = 0.f; }
        } else {
            int gk = k0 + bk1;
            int gn = colBase + bn1;
            bReg0 = (gn     < N) ? Bm[(long long)gk * N + gn]     : 0.f;
            bReg1 = (gn + 1 < N) ? Bm[(long long)gk * N + gn + 1] : 0.f;
        }
    };
    auto storeTile = [&](int buf) {
        As[buf][ak + 0][am] = aReg.x;
        As[buf][ak + 1][am] = aReg.y;
        As[buf][ak + 2][am] = aReg.z;
        As[buf][ak + 3][am] = aReg.w;
        if (b_kn == 0) {
            Bs[buf][bk0 + 0][bn0] = bReg0;
            Bs[buf][bk0 + 1][bn0] = bReg1;
        } else {
            Bs[buf][bk1][bn1 + 0] = bReg0;
            Bs[buf][bk1][bn1 + 1] = bReg1;
        }
    };

    // accumulators: [row-pair ip][col j]; each ull = rows (2ip, 2ip+1) of col j
    ull accT[4][4] = {};   // running total (sum of completed kc-panels)
    ull accP[4][4] = {};   // current panel chains

    loadA(0); loadB(0);
    storeTile(0);
    __syncthreads();

    int cur = 0;
    for (int k0 = 0; k0 < K; k0 += BK) {
        const bool hasNext = (k0 + BK) < K;
        if (hasNext) { loadA(k0 + BK); loadB(k0 + BK); }

        #pragma unroll
        for (int k = 0; k < BK; k++) {     // ascending k within panel
            const float4* As4 = reinterpret_cast<const float4*>(&As[cur][k][0]);
            const float4* Bs4 = reinterpret_cast<const float4*>(&Bs[cur][k][0]);
            float4 a01 = As4[ty * 2];      // rows 0..3 of this thread
            float4 a23 = As4[ty * 2 + 1];  // rows 4..7
            float4 b   = Bs4[tx];

            ull ap[4];
            ap[0] = pack2(a01.x, a01.y);   // rows (0,1)
            ap[1] = pack2(a01.z, a01.w);   // rows (2,3)
            ap[2] = pack2(a23.x, a23.y);   // rows (4,5)
            ap[3] = pack2(a23.z, a23.w);   // rows (6,7)
            ull bb[4];
            bb[0] = pack2(b.x, b.x);
            bb[1] = pack2(b.y, b.y);
            bb[2] = pack2(b.z, b.z);
            bb[3] = pack2(b.w, b.w);

            #pragma unroll
            for (int ip = 0; ip < 4; ip++)
                #pragma unroll
                for (int j = 0; j < 4; j++)
                    accP[ip][j] = ffma2(ap[ip], bb[j], accP[ip][j]);
        }

        // Eigen kc-panel boundary: fold panel chains into totals, restart.
        if ((((k0 + BK) % kc) == 0) || !hasNext) {
            #pragma unroll
            for (int ip = 0; ip < 4; ip++)
                #pragma unroll
                for (int j = 0; j < 4; j++) {
                    accT[ip][j] = fadd2(accT[ip][j], accP[ip][j]);
                    accP[ip][j] = 0ull;
                }
        }

        if (hasNext) storeTile(cur ^ 1);
        __syncthreads();
        cur ^= 1;
    }

    #pragma unroll
    for (int ip = 0; ip < 4; ip++) {
        #pragma unroll
        for (int j = 0; j < 4; j++) {
            int gn = colBase + tx * 4 + j;
            if (gn >= N) continue;
            float lo, hi;
            unpack2(accT[ip][j], lo, hi);
            int gr0 = rowBase + ty * 8 + ip * 2;       // M % 128 == 0 -> valid
            // row 2*ip
            {
                float v = alpha * lo;
                if (bias) v += bias[gn];
                if (res)  v += res[(long long)gr0 * N + gn];
                if (spike) v = (v > thr) ? 1.0f : 0.0f;
                C[(long long)gr0 * N + gn] = v;
            }
            // row 2*ip+1
            {
                float v = alpha * hi;
                if (bias) v += bias[gn];
                if (res)  v += res[(long long)(gr0 + 1) * N + gn];
                if (spike) v = (v > thr) ? 1.0f : 0.0f;
                C[(long long)(gr0 + 1) * N + gn] = v;
            }
        }
    }
}

// row softmax over 512 columns; one block (256 threads) per row.
__global__ __launch_bounds__(256)
void softmax512_kernel(float* __restrict__ attn)
{
    long long row = blockIdx.x;
    float* p = attn + row * (long long)S_;
    int t = threadIdx.x;
    float v0 = p[t], v1 = p[t + 256];

    __shared__ float  redf[8];
    __shared__ double redd[8];

    float m = fmaxf(v0, v1);
    #pragma unroll
    for (int o = 16; o; o >>= 1) m = fmaxf(m, __shfl_xor_sync(0xffffffffu, m, o));
    if ((t & 31) == 0) redf[t >> 5] = m;
    __syncthreads();
    float mm = redf[0];
    #pragma unroll
    for (int i = 1; i < 8; i++) mm = fmaxf(mm, redf[i]);
    __syncthreads();

    float e0 = (float)exp((double)(v0 - mm));
    float e1 = (float)exp((double)(v1 - mm));

    double s = (double)e0 + (double)e1;
    #pragma unroll
    for (int o = 16; o; o >>= 1) s += __shfl_xor_sync(0xffffffffu, s, o);
    if ((t & 31) == 0) redd[t >> 5] = s;
    __syncthreads();
    double stot_d = 0.0;
    #pragma unroll
    for (int i = 0; i < 8; i++) stot_d += redd[i];
    float stot = (float)stot_d;

    p[t]       = e0 / stot;   // IEEE fp32 divide
    p[t + 256] = e1 / stot;
}

// final layer: cur3 = spk2 @ W3^T (K=200 < 320: single panel, ascending chain),
// + b3 last; spk3 = cur3>0.3; mem3 = cur3 - 0.3*spk3
__global__ __launch_bounds__(64)
void final_kernel(const float* __restrict__ spk2,
                  const float* __restrict__ W3,
                  const float* __restrict__ b3,
                  float* __restrict__ out)
{
    int r = blockIdx.x;
    __shared__ float row[DH2];
    for (int i = threadIdx.x; i < DH2; i += blockDim.x)
        row[i] = spk2[(long long)r * DH2 + i];
    __syncthreads();
    if (threadIdx.x < DOUT) {
        int o = threadIdx.x;
        float acc = 0.0f;
        for (int k = 0; k < DH2; k++)
            acc = fmaf(row[k], W3[o * DH2 + k], acc);
        acc += b3[o];
        float spk = (acc > 0.3f) ? 1.0f : 0.0f;
        out[(long long)r * DOUT + o] = spk;
        out[(long long)MROWS * DOUT + (long long)r * DOUT + o] = acc - spk * 0.3f;
    }
}

// ---------------- launch ----------------
extern "C" void kernel_launch(void* const* d_in, const int* in_sizes, int n_in,
                              void* d_out, int out_size)
{
    const float* x  = (const float*)d_in[0];
    const float* We = (const float*)d_in[1];
    const float* be = (const float*)d_in[2];
    const float* Wq = (const float*)d_in[3];
    const float* bq = (const float*)d_in[4];
    const float* Wk = (const float*)d_in[5];
    const float* bk = (const float*)d_in[6];
    const float* Wv = (const float*)d_in[7];
    const float* bv = (const float*)d_in[8];
    const float* W2 = (const float*)d_in[9];
    const float* b2 = (const float*)d_in[10];
    const float* W3 = (const float*)d_in[11];
    const float* b3 = (const float*)d_in[12];
    float* out = (float*)d_out;

    float *spk1, *Qb, *Kb, *Vb, *attn, *attnout, *spk2;
    cudaGetSymbolAddress((void**)&spk1,    d_spk1);
    cudaGetSymbolAddress((void**)&Qb,      d_Q);
    cudaGetSymbolAddress((void**)&Kb,      d_K);
    cudaGetSymbolAddress((void**)&Vb,      d_V);
    cudaGetSymbolAddress((void**)&attn,    d_attn);
    cudaGetSymbolAddress((void**)&attnout, d_attnout);
    cudaGetSymbolAddress((void**)&spk2,    d_spk2);

    // 1) global max of x (for the /255 branch)
    reset_kernel<<<1, 1>>>();
    reduce_max_kernel<<<512, 256>>>(x, MROWS * DIN);

    // 2) embed + LIF1 -> spk1 (K=784: panels 320,320,144)
    gemm_kernel<<<dim3((DEMB + BN - 1) / BN, MROWS / BM, 1), 256>>>(
        x, We, be, nullptr, spk1, MROWS, DEMB, DIN, KC_MAIN,
        0, 0, 0, 1.0f, 0, 1, 0.5f, 1);

    // 3) Q, K, V (K=600: panels 320,280)
    gemm_kernel<<<dim3(1, MROWS / BM, 1), 256>>>(
        spk1, Wq, bq, nullptr, Qb, MROWS, DQK, DEMB, KC_MAIN,
        0, 0, 0, 1.0f, 0, 0, 0.f, 0);
    gemm_kernel<<<dim3(1, MROWS / BM, 1), 256>>>(
        spk1, Wk, bk, nullptr, Kb, MROWS, DQK, DEMB, KC_MAIN,
        0, 0, 0, 1.0f, 0, 0, 0.f, 0);
    gemm_kernel<<<dim3((DEMB + BN - 1) / BN, MROWS / BM, 1), 256>>>(
        spk1, Wv, bv, nullptr, Vb, MROWS, DEMB, DEMB, KC_MAIN,
        0, 0, 0, 1.0f, 0, 0, 0.f, 0);

    // 4) scores = Q @ K^T * 1/8 (K=64: single panel)
    gemm_kernel<<<dim3(S_ / BN, S_ / BM, B_), 256>>>(
        Qb, Kb, nullptr, nullptr, attn, S_, S_, DQK, KC_MAIN,
        (long long)S_ * DQK, (long long)S_ * DQK, (long long)S_ * S_,
        0.125f, 0, 0, 0.f, 0);

    // 5) softmax rows
    softmax512_kernel<<<B_ * S_, 256>>>(attn);

    // 6) attn_out = attn @ V + spk1 (K=512: panels 320,192); V is [K,N] per batch
    gemm_kernel<<<dim3((DEMB + BN - 1) / BN, S_ / BM, B_), 256>>>(
        attn, Vb, nullptr, spk1, attnout, S_, DEMB, S_, KC_MAIN,
        (long long)S_ * S_, (long long)S_ * DEMB, (long long)S_ * DEMB,
        1.0f, 1, 0, 0.f, 0);

    // 7) cur2 + LIF2 -> spk2 (K=600: panels 320,280)
    gemm_kernel<<<dim3((DH2 + BN - 1) / BN, MROWS / BM, 1), 256>>>(
        attnout, W2, b2, nullptr, spk2, MROWS, DH2, DEMB, KC_MAIN,
        0, 0, 0, 1.0f, 0, 1, 0.3f, 0);

    // 8) final layer -> (spk3, mem3)
    final_kernel<<<MROWS, 64>>>(spk2, W3, b3, out);

    (void)in_sizes; (void)n_in; (void)out_size;
}

// round 8
// speedup vs baseline: 1.0890x; 1.0890x over previous
#include <cuda_runtime.h>
#include <cuda_bf16.h>
#include <math.h>

// ---------------- problem dims ----------------
#define B_   64
#define S_   512
#define DIN  784
#define DEMB 600
#define DQK  64
#define DH2  200
#define DOUT 10
#define MROWS (B_*S_)   // 32768

// Eigen MT gebp K-panel size (confirmed bit-exact in R5): kc = 320
#define KC_MAIN 320

// ---------------- scratch (device globals: no allocation allowed) ----------------
__device__ unsigned int g_max_u;
static __device__ float d_spk1   [(size_t)MROWS*DEMB];
static __device__ float d_Q      [(size_t)MROWS*DQK];
static __device__ float d_K      [(size_t)MROWS*DQK];
static __device__ float d_V      [(size_t)MROWS*DEMB];
static __device__ float d_attn   [(size_t)B_*S_*S_];
static __device__ float d_attnout[(size_t)MROWS*DEMB];
static __device__ float d_spk2   [(size_t)MROWS*DH2];

// ---------------- packed fp32x2 helpers (lane-wise IEEE RN: bit-exact) ----------------
typedef unsigned long long ull;
__device__ __forceinline__ void unpack2(ull v, float& lo, float& hi) {
    asm("mov.b64 {%0, %1}, %2;" : "=f"(lo), "=f"(hi) : "l"(v));
}
__device__ __forceinline__ ull ffma2(ull a, ull b, ull c) {
    ull d; asm("fma.rn.f32x2 %0, %1, %2, %3;" : "=l"(d) : "l"(a), "l"(b), "l"(c)); return d;
}
__device__ __forceinline__ ull fadd2(ull a, ull b) {
    ull d; asm("add.rn.f32x2 %0, %1, %2;" : "=l"(d) : "l"(a), "l"(b)); return d;
}

// ---------------- kernels ----------------
__global__ void reset_kernel() { g_max_u = 0u; }

__global__ void reduce_max_kernel(const float* __restrict__ x, int n) {
    float m = 0.f;
    for (int i = blockIdx.x * blockDim.x + threadIdx.x; i < n; i += gridDim.x * blockDim.x)
        m = fmaxf(m, x[i]);
    #pragma unroll
    for (int o = 16; o; o >>= 1) m = fmaxf(m, __shfl_xor_sync(0xffffffffu, m, o));
    if ((threadIdx.x & 31) == 0) atomicMax(&g_max_u, __float_as_uint(m)); // x >= 0
}

// Tiled fp32 GEMM emulating Eigen gebp accumulation order (BIT-EXACT vs R5/R6):
//   per output: ascending-k fmaf chain, folded into a running total at kc panel
//   boundaries (last panel = remainder). FFMA2 pairs adjacent-ROW chains; each
//   scalar slot's chain is unchanged. Pairs are formed IN SMEM (A naturally
//   adjacent; B stored duplicated) so the inner loop has zero packing MOVs:
//   per k-step: 4x LDS.128 + 16x FFMA2.
//   A: [M,K] row-major; B: b_kn==0 -> [N,K], b_kn==1 -> [K,N]
//   batched via blockIdx.z with strides sA,sB,sC (res uses sC).
// Tiling: BM=128, BN=64, BK=8, 256 threads, 8x4 per-thread tile.
// Requires: M % 128 == 0, K % 8 == 0 (true for every call site).
#define BM 128
#define BN 64
#define BK 8
__global__ __launch_bounds__(256, 2)
void gemm_kernel(const float* __restrict__ A,
                 const float* __restrict__ Bm,
                 const float* __restrict__ bias,
                 const float* __restrict__ res,
                 float* __restrict__ C,
                 int M, int N, int K, int kc,
                 long long sA, long long sB, long long sC,
                 float alpha, int b_kn, int spike, float thr, int scaleA)
{
    __shared__ float As [2][BK][BM];        // rows contiguous -> natural pairs
    __shared__ float Bsd[2][BK][BN * 2];    // duplicated: Bsd[k][2n]=Bsd[k][2n+1]=b[n]

    long long bz = blockIdx.z;
    A  += bz * sA;
    Bm += bz * sB;
    C  += bz * sC;
    if (res) res += bz * sC;

    const int rowBase = blockIdx.y * BM;
    const int colBase = blockIdx.x * BN;
    const int t  = threadIdx.x;            // 256 threads
    const int tx = t & 15;                 // 16 cols of 4
    const int ty = t >> 4;                 // 16 rows of 8

    float sc = 1.0f;
    if (scaleA) sc = (__uint_as_float(g_max_u) > 1.0f) ? (1.0f / 255.0f) : 1.0f;

    // ---- staging register indices ----
    const int am = t >> 1;                 // A: float4 at (m=t>>1, k=(t&1)*4)
    const int ak = (t & 1) * 4;
    const int bn0 = t >> 2;                // B [N,K]: float2 at (n=t>>2, k=(t&3)*2)
    const int bk0 = (t & 3) * 2;
    const int bk1 = t >> 5;                // B [K,N]: 2 scalars at (k=t>>5, n=(t&31)*2)
    const int bn1 = (t & 31) * 2;

    float4 aReg;
    float  bReg0, bReg1;

    auto loadA = [&](int k0) {
        aReg = *reinterpret_cast<const float4*>(A + (long long)(rowBase + am) * K + (k0 + ak));
        aReg.x *= sc; aReg.y *= sc; aReg.z *= sc; aReg.w *= sc;
    };
    auto loadB = [&](int k0) {
        if (b_kn == 0) {
            int gn = colBase + bn0;
            if (gn < N) {
                float2 v = *reinterpret_cast<const float2*>(Bm + (long long)gn * K + (k0 + bk0));
                bReg0 = v.x; bReg1 = v.y;
            } else { bReg0 = 0.f; bReg1 = 0.f; }
        } else {
            int gk = k0 + bk1;
            int gn = colBase + bn1;
            bReg0 = (gn     < N) ? Bm[(long long)gk * N + gn]     : 0.f;
            bReg1 = (gn + 1 < N) ? Bm[(long long)gk * N + gn + 1] : 0.f;
        }
    };
    auto storeTile = [&](int buf) {
        As[buf][ak + 0][am] = aReg.x;
        As[buf][ak + 1][am] = aReg.y;
        As[buf][ak + 2][am] = aReg.z;
        As[buf][ak + 3][am] = aReg.w;
        if (b_kn == 0) {
            // (n=bn0, k=bk0) and (n=bn0, k=bk0+1), duplicated along n
            *reinterpret_cast<float2*>(&Bsd[buf][bk0 + 0][bn0 * 2]) = make_float2(bReg0, bReg0);
            *reinterpret_cast<float2*>(&Bsd[buf][bk0 + 1][bn0 * 2]) = make_float2(bReg1, bReg1);
        } else {
            // (k=bk1, n=bn1) and (k=bk1, n=bn1+1), duplicated along n
            *reinterpret_cast<float2*>(&Bsd[buf][bk1][(bn1 + 0) * 2]) = make_float2(bReg0, bReg0);
            *reinterpret_cast<float2*>(&Bsd[buf][bk1][(bn1 + 1) * 2]) = make_float2(bReg1, bReg1);
        }
    };

    // accumulators: [row-pair ip][col j]; each ull = rows (2ip, 2ip+1) of col j
    ull accT[4][4] = {};   // running total (sum of completed kc-panels)
    ull accP[4][4] = {};   // current panel chains

    loadA(0); loadB(0);
    storeTile(0);
    __syncthreads();

    int cur = 0;
    for (int k0 = 0; k0 < K; k0 += BK) {
        const bool hasNext = (k0 + BK) < K;
        if (hasNext) { loadA(k0 + BK); loadB(k0 + BK); }

        #pragma unroll
        for (int k = 0; k < BK; k++) {     // ascending k within panel
            // A row-pairs: 2x LDS.128, each = two ull pairs (rows 0-3, 4-7)
            const ulonglong2* Ap = reinterpret_cast<const ulonglong2*>(&As[cur][k][ty * 8]);
            ulonglong2 a01 = Ap[0];        // .x = rows(0,1), .y = rows(2,3)
            ulonglong2 a23 = Ap[1];        // .x = rows(4,5), .y = rows(6,7)
            // B duplicated pairs: 2x LDS.128, each = two {b,b} ulls
            const ulonglong2* Bp = reinterpret_cast<const ulonglong2*>(&Bsd[cur][k][tx * 8]);
            ulonglong2 b01 = Bp[0];        // .x = {b0,b0}, .y = {b1,b1}
            ulonglong2 b23 = Bp[1];        // .x = {b2,b2}, .y = {b3,b3}

            ull ap[4] = {a01.x, a01.y, a23.x, a23.y};
            ull bb[4] = {b01.x, b01.y, b23.x, b23.y};

            #pragma unroll
            for (int ip = 0; ip < 4; ip++)
                #pragma unroll
                for (int j = 0; j < 4; j++)
                    accP[ip][j] = ffma2(ap[ip], bb[j], accP[ip][j]);
        }

        // Eigen kc-panel boundary: fold panel chains into totals, restart.
        if ((((k0 + BK) % kc) == 0) || !hasNext) {
            #pragma unroll
            for (int ip = 0; ip < 4; ip++)
                #pragma unroll
                for (int j = 0; j < 4; j++) {
                    accT[ip][j] = fadd2(accT[ip][j], accP[ip][j]);
                    accP[ip][j] = 0ull;
                }
        }

        if (hasNext) storeTile(cur ^ 1);
        __syncthreads();
        cur ^= 1;
    }

    #pragma unroll
    for (int ip = 0; ip < 4; ip++) {
        #pragma unroll
        for (int j = 0; j < 4; j++) {
            int gn = colBase + tx * 4 + j;
            if (gn >= N) continue;
            float lo, hi;
            unpack2(accT[ip][j], lo, hi);
            int gr0 = rowBase + ty * 8 + ip * 2;       // M % 128 == 0 -> valid
            {
                float v = alpha * lo;
                if (bias) v += bias[gn];
                if (res)  v += res[(long long)gr0 * N + gn];
                if (spike) v = (v > thr) ? 1.0f : 0.0f;
                C[(long long)gr0 * N + gn] = v;
            }
            {
                float v = alpha * hi;
                if (bias) v += bias[gn];
                if (res)  v += res[(long long)(gr0 + 1) * N + gn];
                if (spike) v = (v > thr) ? 1.0f : 0.0f;
                C[(long long)(gr0 + 1) * N + gn] = v;
            }
        }
    }
}

// row softmax over 512 columns; one block (256 threads) per row.
__global__ __launch_bounds__(256)
void softmax512_kernel(float* __restrict__ attn)
{
    long long row = blockIdx.x;
    float* p = attn + row * (long long)S_;
    int t = threadIdx.x;
    float v0 = p[t], v1 = p[t + 256];

    __shared__ float  redf[8];
    __shared__ double redd[8];

    float m = fmaxf(v0, v1);
    #pragma unroll
    for (int o = 16; o; o >>= 1) m = fmaxf(m, __shfl_xor_sync(0xffffffffu, m, o));
    if ((t & 31) == 0) redf[t >> 5] = m;
    __syncthreads();
    float mm = redf[0];
    #pragma unroll
    for (int i = 1; i < 8; i++) mm = fmaxf(mm, redf[i]);
    __syncthreads();

    float e0 = (float)exp((double)(v0 - mm));
    float e1 = (float)exp((double)(v1 - mm));

    double s = (double)e0 + (double)e1;
    #pragma unroll
    for (int o = 16; o; o >>= 1) s += __shfl_xor_sync(0xffffffffu, s, o);
    if ((t & 31) == 0) redd[t >> 5] = s;
    __syncthreads();
    double stot_d = 0.0;
    #pragma unroll
    for (int i = 0; i < 8; i++) stot_d += redd[i];
    float stot = (float)stot_d;

    p[t]       = e0 / stot;   // IEEE fp32 divide
    p[t + 256] = e1 / stot;
}

// final layer: cur3 = spk2 @ W3^T (K=200 < 320: single panel, ascending chain),
// + b3 last; spk3 = cur3>0.3; mem3 = cur3 - 0.3*spk3
__global__ __launch_bounds__(64)
void final_kernel(const float* __restrict__ spk2,
                  const float* __restrict__ W3,
                  const float* __restrict__ b3,
                  float* __restrict__ out)
{
    int r = blockIdx.x;
    __shared__ float row[DH2];
    for (int i = threadIdx.x; i < DH2; i += blockDim.x)
        row[i] = spk2[(long long)r * DH2 + i];
    __syncthreads();
    if (threadIdx.x < DOUT) {
        int o = threadIdx.x;
        float acc = 0.0f;
        for (int k = 0; k < DH2; k++)
            acc = fmaf(row[k], W3[o * DH2 + k], acc);
        acc += b3[o];
        float spk = (acc > 0.3f) ? 1.0f : 0.0f;
        out[(long long)r * DOUT + o] = spk;
        out[(long long)MROWS * DOUT + (long long)r * DOUT + o] = acc - spk * 0.3f;
    }
}

// ---------------- launch ----------------
extern "C" void kernel_launch(void* const* d_in, const int* in_sizes, int n_in,
                              void* d_out, int out_size)
{
    const float* x  = (const float*)d_in[0];
    const float* We = (const float*)d_in[1];
    const float* be = (const float*)d_in[2];
    const float* Wq = (const float*)d_in[3];
    const float* bq = (const float*)d_in[4];
    const float* Wk = (const float*)d_in[5];
    const float* bk = (const float*)d_in[6];
    const float* Wv = (const float*)d_in[7];
    const float* bv = (const float*)d_in[8];
    const float* W2 = (const float*)d_in[9];
    const float* b2 = (const float*)d_in[10];
    const float* W3 = (const float*)d_in[11];
    const float* b3 = (const float*)d_in[12];
    float* out = (float*)d_out;

    float *spk1, *Qb, *Kb, *Vb, *attn, *attnout, *spk2;
    cudaGetSymbolAddress((void**)&spk1,    d_spk1);
    cudaGetSymbolAddress((void**)&Qb,      d_Q);
    cudaGetSymbolAddress((void**)&Kb,      d_K);
    cudaGetSymbolAddress((void**)&Vb,      d_V);
    cudaGetSymbolAddress((void**)&attn,    d_attn);
    cudaGetSymbolAddress((void**)&attnout, d_attnout);
    cudaGetSymbolAddress((void**)&spk2,    d_spk2);

    // 1) global max of x (for the /255 branch)
    reset_kernel<<<1, 1>>>();
    reduce_max_kernel<<<512, 256>>>(x, MROWS * DIN);

    // 2) embed + LIF1 -> spk1 (K=784: panels 320,320,144)
    gemm_kernel<<<dim3((DEMB + BN - 1) / BN, MROWS / BM, 1), 256>>>(
        x, We, be, nullptr, spk1, MROWS, DEMB, DIN, KC_MAIN,
        0, 0, 0, 1.0f, 0, 1, 0.5f, 1);

    // 3) Q, K, V (K=600: panels 320,280)
    gemm_kernel<<<dim3(1, MROWS / BM, 1), 256>>>(
        spk1, Wq, bq, nullptr, Qb, MROWS, DQK, DEMB, KC_MAIN,
        0, 0, 0, 1.0f, 0, 0, 0.f, 0);
    gemm_kernel<<<dim3(1, MROWS / BM, 1), 256>>>(
        spk1, Wk, bk, nullptr, Kb, MROWS, DQK, DEMB, KC_MAIN,
        0, 0, 0, 1.0f, 0, 0, 0.f, 0);
    gemm_kernel<<<dim3((DEMB + BN - 1) / BN, MROWS / BM, 1), 256>>>(
        spk1, Wv, bv, nullptr, Vb, MROWS, DEMB, DEMB, KC_MAIN,
        0, 0, 0, 1.0f, 0, 0, 0.f, 0);

    // 4) scores = Q @ K^T * 1/8 (K=64: single panel)
    gemm_kernel<<<dim3(S_ / BN, S_ / BM, B_), 256>>>(
        Qb, Kb, nullptr, nullptr, attn, S_, S_, DQK, KC_MAIN,
        (long long)S_ * DQK, (long long)S_ * DQK, (long long)S_ * S_,
        0.125f, 0, 0, 0.f, 0);

    // 5) softmax rows
    softmax512_kernel<<<B_ * S_, 256>>>(attn);

    // 6) attn_out = attn @ V + spk1 (K=512: panels 320,192); V is [K,N] per batch
    gemm_kernel<<<dim3((DEMB + BN - 1) / BN, S_ / BM, B_), 256>>>(
        attn, Vb, nullptr, spk1, attnout, S_, DEMB, S_, KC_MAIN,
        (long long)S_ * S_, (long long)S_ * DEMB, (long long)S_ * DEMB,
        1.0f, 1, 0, 0.f, 0);

    // 7) cur2 + LIF2 -> spk2 (K=600: panels 320,280)
    gemm_kernel<<<dim3((DH2 + BN - 1) / BN, MROWS / BM, 1), 256>>>(
        attnout, W2, b2, nullptr, spk2, MROWS, DH2, DEMB, KC_MAIN,
        0, 0, 0, 1.0f, 0, 1, 0.3f, 0);

    // 8) final layer -> (spk3, mem3)
    final_kernel<<<MROWS, 64>>>(spk2, W3, b3, out);

    (void)in_sizes; (void)n_in; (void)out_size;
}

// round 9
// speedup vs baseline: 1.6096x; 1.4781x over previous
#include <cuda_runtime.h>
#include <cuda_bf16.h>
#include <math.h>

// ---------------- problem dims ----------------
#define B_   64
#define S_   512
#define DIN  784
#define DEMB 600
#define DQK  64
#define DH2  200
#define DOUT 10
#define MROWS (B_*S_)   // 32768

// Eigen MT gebp K-panel size (confirmed bit-exact in R5): kc = 320
#define KC_MAIN 320

// ---------------- scratch (device globals: no allocation allowed) ----------------
__device__ unsigned int g_max_u;
static __device__ float d_spk1   [(size_t)MROWS*DEMB];
static __device__ float d_Q      [(size_t)MROWS*DQK];
static __device__ float d_K      [(size_t)MROWS*DQK];
static __device__ float d_V      [(size_t)MROWS*DEMB];
static __device__ float d_attn   [(size_t)B_*S_*S_];
static __device__ float d_attnout[(size_t)MROWS*DEMB];
static __device__ float d_spk2   [(size_t)MROWS*DH2];

// ---------------- kernels ----------------
__global__ void reset_kernel() { g_max_u = 0u; }

__global__ void reduce_max_kernel(const float* __restrict__ x, int n) {
    float m = 0.f;
    for (int i = blockIdx.x * blockDim.x + threadIdx.x; i < n; i += gridDim.x * blockDim.x)
        m = fmaxf(m, x[i]);
    #pragma unroll
    for (int o = 16; o; o >>= 1) m = fmaxf(m, __shfl_xor_sync(0xffffffffu, m, o));
    if ((threadIdx.x & 31) == 0) atomicMax(&g_max_u, __float_as_uint(m)); // x >= 0
}

// Tiled fp32 GEMM emulating Eigen gebp accumulation order (BIT-EXACT vs R5/R6):
//   per output: ascending-k fmaf chain (accP registers), folded into a running
//   total at kc panel boundaries (last panel = remainder). The running totals
//   (accT) live in SHARED MEMORY (touched only at folds) to cut registers from
//   128 -> ~70 and allow 3 blocks/SM instead of 2 (occupancy was the R6 binder:
//   fma pipe busy only 31% at occ 21.7%).
//   A: [M,K] row-major; B: b_kn==0 -> [N,K], b_kn==1 -> [K,N]
//   batched via blockIdx.z with strides sA,sB,sC (res uses sC).
// Tiling: BM=128, BN=64, BK=8, 256 threads, 8x4 per-thread tile.
// Requires: M % 128 == 0, K % 8 == 0 (true for every call site).
#define BM 128
#define BN 64
#define BK 8
__global__ __launch_bounds__(256, 3)
void gemm_kernel(const float* __restrict__ A,
                 const float* __restrict__ Bm,
                 const float* __restrict__ bias,
                 const float* __restrict__ res,
                 float* __restrict__ C,
                 int M, int N, int K, int kc,
                 long long sA, long long sB, long long sC,
                 float alpha, int b_kn, int spike, float thr, int scaleA)
{
    __shared__ float As[2][BK][BM];
    __shared__ float Bs[2][BK][BN];
    // Panel running totals: one column per thread -> every lane hits its own
    // bank (stride 256 floats) -> conflict-free. 32KB.
    __shared__ float accTs[32][256];

    long long bz = blockIdx.z;
    A  += bz * sA;
    Bm += bz * sB;
    C  += bz * sC;
    if (res) res += bz * sC;

    const int rowBase = blockIdx.y * BM;
    const int colBase = blockIdx.x * BN;
    const int t  = threadIdx.x;            // 256 threads
    const int tx = t & 15;                 // 16 cols of 4
    const int ty = t >> 4;                 // 16 rows of 8

    float sc = 1.0f;
    if (scaleA) sc = (__uint_as_float(g_max_u) > 1.0f) ? (1.0f / 255.0f) : 1.0f;

    // ---- staging register indices ----
    const int am = t >> 1;                 // A: float4 at (m=t>>1, k=(t&1)*4)
    const int ak = (t & 1) * 4;
    const int bn0 = t >> 2;                // B [N,K]: float2 at (n=t>>2, k=(t&3)*2)
    const int bk0 = (t & 3) * 2;
    const int bk1 = t >> 5;                // B [K,N]: 2 scalars at (k=t>>5, n=(t&31)*2)
    const int bn1 = (t & 31) * 2;

    float4 aReg;
    float  bReg0, bReg1;

    auto loadA = [&](int k0) {
        aReg = *reinterpret_cast<const float4*>(A + (long long)(rowBase + am) * K + (k0 + ak));
        aReg.x *= sc; aReg.y *= sc; aReg.z *= sc; aReg.w *= sc;
    };
    auto loadB = [&](int k0) {
        if (b_kn == 0) {
            int gn = colBase + bn0;
            if (gn < N) {
                float2 v = *reinterpret_cast<const float2*>(Bm + (long long)gn * K + (k0 + bk0));
                bReg0 = v.x; bReg1 = v.y;
            } else { bReg0 = 0.f; bReg1 = 0.f; }
        } else {
            int gk = k0 + bk1;
            int gn = colBase + bn1;
            bReg0 = (gn     < N) ? Bm[(long long)gk * N + gn]     : 0.f;
            bReg1 = (gn + 1 < N) ? Bm[(long long)gk * N + gn + 1] : 0.f;
        }
    };
    auto storeTile = [&](int buf) {
        As[buf][ak + 0][am] = aReg.x;
        As[buf][ak + 1][am] = aReg.y;
        As[buf][ak + 2][am] = aReg.z;
        As[buf][ak + 3][am] = aReg.w;
        if (b_kn == 0) {
            Bs[buf][bk0 + 0][bn0] = bReg0;
            Bs[buf][bk0 + 1][bn0] = bReg1;
        } else {
            Bs[buf][bk1][bn1 + 0] = bReg0;
            Bs[buf][bk1][bn1 + 1] = bReg1;
        }
    };

    // zero my accT column (each thread touches only its own column: no sync needed)
    #pragma unroll
    for (int s = 0; s < 32; s++) accTs[s][t] = 0.f;

    float accP[8][4] = {};   // current panel chains (hot registers)

    loadA(0); loadB(0);
    storeTile(0);
    __syncthreads();

    int cur = 0;
    for (int k0 = 0; k0 < K; k0 += BK) {
        const bool hasNext = (k0 + BK) < K;
        if (hasNext) { loadA(k0 + BK); loadB(k0 + BK); }

        #pragma unroll
        for (int k = 0; k < BK; k++) {     // ascending k within panel
            const float4* As4 = reinterpret_cast<const float4*>(&As[cur][k][0]);
            const float4* Bs4 = reinterpret_cast<const float4*>(&Bs[cur][k][0]);
            float4 a01 = As4[ty * 2];
            float4 a23 = As4[ty * 2 + 1];
            float4 b   = Bs4[tx];
            float a_[8] = {a01.x, a01.y, a01.z, a01.w, a23.x, a23.y, a23.z, a23.w};
            float b_[4] = {b.x, b.y, b.z, b.w};
            #pragma unroll
            for (int i = 0; i < 8; i++)
                #pragma unroll
                for (int j = 0; j < 4; j++)
                    accP[i][j] = fmaf(a_[i], b_[j], accP[i][j]);
        }

        // Eigen kc-panel boundary: fold panel chain into smem totals, restart.
        if ((((k0 + BK) % kc) == 0) || !hasNext) {
            #pragma unroll
            for (int i = 0; i < 8; i++)
                #pragma unroll
                for (int j = 0; j < 4; j++) {
                    accTs[i * 4 + j][t] += accP[i][j];   // scalar IEEE add: exact order kept
                    accP[i][j] = 0.f;
                }
        }

        if (hasNext) storeTile(cur ^ 1);
        __syncthreads();
        cur ^= 1;
    }

    #pragma unroll
    for (int i = 0; i < 8; i++) {
        int gr = rowBase + ty * 8 + i;     // M % 128 == 0 -> always valid
        #pragma unroll
        for (int j = 0; j < 4; j++) {
            int gn = colBase + tx * 4 + j;
            if (gn >= N) continue;
            float v = alpha * accTs[i * 4 + j][t];  // alpha = 1.0 or 0.125 (exact)
            if (bias) v += bias[gn];
            if (res)  v += res[(long long)gr * N + gn];
            if (spike) v = (v > thr) ? 1.0f : 0.0f;
            C[(long long)gr * N + gn] = v;
        }
    }
}

// row softmax over 512 columns; one block (256 threads) per row.
__global__ __launch_bounds__(256)
void softmax512_kernel(float* __restrict__ attn)
{
    long long row = blockIdx.x;
    float* p = attn + row * (long long)S_;
    int t = threadIdx.x;
    float v0 = p[t], v1 = p[t + 256];

    __shared__ float  redf[8];
    __shared__ double redd[8];

    float m = fmaxf(v0, v1);
    #pragma unroll
    for (int o = 16; o; o >>= 1) m = fmaxf(m, __shfl_xor_sync(0xffffffffu, m, o));
    if ((t & 31) == 0) redf[t >> 5] = m;
    __syncthreads();
    float mm = redf[0];
    #pragma unroll
    for (int i = 1; i < 8; i++) mm = fmaxf(mm, redf[i]);
    __syncthreads();

    float e0 = (float)exp((double)(v0 - mm));
    float e1 = (float)exp((double)(v1 - mm));

    double s = (double)e0 + (double)e1;
    #pragma unroll
    for (int o = 16; o; o >>= 1) s += __shfl_xor_sync(0xffffffffu, s, o);
    if ((t & 31) == 0) redd[t >> 5] = s;
    __syncthreads();
    double stot_d = 0.0;
    #pragma unroll
    for (int i = 0; i < 8; i++) stot_d += redd[i];
    float stot = (float)stot_d;

    p[t]       = e0 / stot;   // IEEE fp32 divide
    p[t + 256] = e1 / stot;
}

// final layer: cur3 = spk2 @ W3^T (K=200 < 320: single panel, ascending chain),
// + b3 last; spk3 = cur3>0.3; mem3 = cur3 - 0.3*spk3
__global__ __launch_bounds__(64)
void final_kernel(const float* __restrict__ spk2,
                  const float* __restrict__ W3,
                  const float* __restrict__ b3,
                  float* __restrict__ out)
{
    int r = blockIdx.x;
    __shared__ float row[DH2];
    for (int i = threadIdx.x; i < DH2; i += blockDim.x)
        row[i] = spk2[(long long)r * DH2 + i];
    __syncthreads();
    if (threadIdx.x < DOUT) {
        int o = threadIdx.x;
        float acc = 0.0f;
        for (int k = 0; k < DH2; k++)
            acc = fmaf(row[k], W3[o * DH2 + k], acc);
        acc += b3[o];
        float spk = (acc > 0.3f) ? 1.0f : 0.0f;
        out[(long long)r * DOUT + o] = spk;
        out[(long long)MROWS * DOUT + (long long)r * DOUT + o] = acc - spk * 0.3f;
    }
}

// ---------------- launch ----------------
extern "C" void kernel_launch(void* const* d_in, const int* in_sizes, int n_in,
                              void* d_out, int out_size)
{
    const float* x  = (const float*)d_in[0];
    const float* We = (const float*)d_in[1];
    const float* be = (const float*)d_in[2];
    const float* Wq = (const float*)d_in[3];
    const float* bq = (const float*)d_in[4];
    const float* Wk = (const float*)d_in[5];
    const float* bk = (const float*)d_in[6];
    const float* Wv = (const float*)d_in[7];
    const float* bv = (const float*)d_in[8];
    const float* W2 = (const float*)d_in[9];
    const float* b2 = (const float*)d_in[10];
    const float* W3 = (const float*)d_in[11];
    const float* b3 = (const float*)d_in[12];
    float* out = (float*)d_out;

    float *spk1, *Qb, *Kb, *Vb, *attn, *attnout, *spk2;
    cudaGetSymbolAddress((void**)&spk1,    d_spk1);
    cudaGetSymbolAddress((void**)&Qb,      d_Q);
    cudaGetSymbolAddress((void**)&Kb,      d_K);
    cudaGetSymbolAddress((void**)&Vb,      d_V);
    cudaGetSymbolAddress((void**)&attn,    d_attn);
    cudaGetSymbolAddress((void**)&attnout, d_attnout);
    cudaGetSymbolAddress((void**)&spk2,    d_spk2);

    // 1) global max of x (for the /255 branch)
    reset_kernel<<<1, 1>>>();
    reduce_max_kernel<<<512, 256>>>(x, MROWS * DIN);

    // 2) embed + LIF1 -> spk1 (K=784: panels 320,320,144)
    gemm_kernel<<<dim3((DEMB + BN - 1) / BN, MROWS / BM, 1), 256>>>(
        x, We, be, nullptr, spk1, MROWS, DEMB, DIN, KC_MAIN,
        0, 0, 0, 1.0f, 0, 1, 0.5f, 1);

    // 3) Q, K, V (K=600: panels 320,280)
    gemm_kernel<<<dim3(1, MROWS / BM, 1), 256>>>(
        spk1, Wq, bq, nullptr, Qb, MROWS, DQK, DEMB, KC_MAIN,
        0, 0, 0, 1.0f, 0, 0, 0.f, 0);
    gemm_kernel<<<dim3(1, MROWS / BM, 1), 256>>>(
        spk1, Wk, bk, nullptr, Kb, MROWS, DQK, DEMB, KC_MAIN,
        0, 0, 0, 1.0f, 0, 0, 0.f, 0);
    gemm_kernel<<<dim3((DEMB + BN - 1) / BN, MROWS / BM, 1), 256>>>(
        spk1, Wv, bv, nullptr, Vb, MROWS, DEMB, DEMB, KC_MAIN,
        0, 0, 0, 1.0f, 0, 0, 0.f, 0);

    // 4) scores = Q @ K^T * 1/8 (K=64: single panel)
    gemm_kernel<<<dim3(S_ / BN, S_ / BM, B_), 256>>>(
        Qb, Kb, nullptr, nullptr, attn, S_, S_, DQK, KC_MAIN,
        (long long)S_ * DQK, (long long)S_ * DQK, (long long)S_ * S_,
        0.125f, 0, 0, 0.f, 0);

    // 5) softmax rows
    softmax512_kernel<<<B_ * S_, 256>>>(attn);

    // 6) attn_out = attn @ V + spk1 (K=512: panels 320,192); V is [K,N] per batch
    gemm_kernel<<<dim3((DEMB + BN - 1) / BN, S_ / BM, B_), 256>>>(
        attn, Vb, nullptr, spk1, attnout, S_, DEMB, S_, KC_MAIN,
        (long long)S_ * S_, (long long)S_ * DEMB, (long long)S_ * DEMB,
        1.0f, 1, 0, 0.f, 0);

    // 7) cur2 + LIF2 -> spk2 (K=600: panels 320,280)
    gemm_kernel<<<dim3((DH2 + BN - 1) / BN, MROWS / BM, 1), 256>>>(
        attnout, W2, b2, nullptr, spk2, MROWS, DH2, DEMB, KC_MAIN,
        0, 0, 0, 1.0f, 0, 1, 0.3f, 0);

    // 8) final layer -> (spk3, mem3)
    final_kernel<<<MROWS, 64>>>(spk2, W3, b3, out);

    (void)in_sizes; (void)n_in; (void)out_size;
}